// round 7
// baseline (speedup 1.0000x reference)
#include <cuda_runtime.h>
#include <cstdint>
#include <math.h>

#define DIM 257
#define SEQ 2048
#define NB  8
#define BT  (NB * SEQ)        // 16384
#define KP  288               // padded K for dim-257 reductions (9 chunks of 32)
#define NPA 384               // padded N for B-operand buffers (3 full 128-tiles)
#define KC  32                // k per pipeline chunk
#define TSTRIDE 36            // smem row stride in floats (bank-conflict-free)
#define TILE_F (128 * TSTRIDE)          // floats per smem tile (4608)
#define SMEM_BYTES (2 * 2 * TILE_F * 4) // 73728

// ---------------- static device scratch (all fp32, tf32-rounded) ----------------
__device__ __align__(16) float g_x[3][(size_t)BT * KP];     // padded q,k,v
__device__ __align__(16) float g_W[4][(size_t)NPA * KP];    // padded weights (K-major)
__device__ __align__(16) float g_b[4][NPA];                 // padded biases
__device__ __align__(16) float g_qp[(size_t)BT * KP];       // projected Q
__device__ __align__(16) float g_kp[(size_t)BT * KP];       // projected K
__device__ __align__(16) float g_vt[(size_t)NB * NPA * SEQ];// V projected, transposed [b][n][t]
__device__ __align__(16) float g_s[(size_t)NB * SEQ * SEQ]; // sigmoid scores
__device__ __align__(16) float g_ct[(size_t)BT * KP];       // context

// ---------------- helpers ----------------
__device__ __forceinline__ float tf32r(float x) {
    uint32_t u;
    asm("cvt.rna.tf32.f32 %0, %1;" : "=r"(u) : "f"(x));
    return __uint_as_float(u);
}
__device__ __forceinline__ uint32_t s2u(const void* p) {
    uint32_t a;
    asm("{ .reg .u64 t; cvta.to.shared.u64 t, %1; cvt.u32.u64 %0, t; }" : "=r"(a) : "l"(p));
    return a;
}
__device__ __forceinline__ void cp16(uint32_t dst, const void* src) {
    asm volatile("cp.async.cg.shared.global [%0], [%1], 16;" :: "r"(dst), "l"(src));
}
__device__ __forceinline__ void mma_tf32(float* d, const uint32_t* a, const uint32_t* b) {
    asm volatile(
        "mma.sync.aligned.m16n8k8.row.col.f32.tf32.tf32.f32 "
        "{%0,%1,%2,%3}, {%4,%5,%6,%7}, {%8,%9}, {%0,%1,%2,%3};"
        : "+f"(d[0]), "+f"(d[1]), "+f"(d[2]), "+f"(d[3])
        : "r"(a[0]), "r"(a[1]), "r"(a[2]), "r"(a[3]), "r"(b[0]), "r"(b[1]));
}

// ---------------- prep kernels (pad + tf32 round) ----------------
__global__ void prep_x(const float* __restrict__ q, const float* __restrict__ k,
                       const float* __restrict__ v) {
    int i = blockIdx.x * 256 + threadIdx.x;
    if (i >= BT * KP) return;
    int r = i / KP, c = i - r * KP;
    long long si = (long long)r * DIM + c;
    g_x[0][i] = (c < DIM) ? tf32r(q[si]) : 0.f;
    g_x[1][i] = (c < DIM) ? tf32r(k[si]) : 0.f;
    g_x[2][i] = (c < DIM) ? tf32r(v[si]) : 0.f;
}
__global__ void prep_w(const float* W0, const float* b0, const float* W1, const float* b1,
                       const float* W2, const float* b2, const float* W3, const float* b3) {
    int i = blockIdx.x * 256 + threadIdx.x;
    const float* Ws[4] = {W0, W1, W2, W3};
    const float* bs[4] = {b0, b1, b2, b3};
    const int per = NPA * KP;
    if (i < 4 * per) {
        int w = i / per, rem = i - w * per, r = rem / KP, c = rem - r * KP;
        g_W[w][(size_t)r * KP + c] = (r < DIM && c < DIM) ? tf32r(Ws[w][r * DIM + c]) : 0.f;
    }
    if (i < 4 * NPA) {
        int w = i / NPA, n = i - w * NPA;
        g_b[w][n] = (n < DIM) ? bs[w][n] : 0.f;
    }
}

// ---------------- tf32 tensor-core GEMM: D[m,n] = sum_k A[m,k]*B[n,k] ----------------
// 128x128 CTA tile, 4 warps, 64x64 warp tile (2x2 warp grid).
// Fragment double-buffering across ks; runtime nf-mask (nmma) skips padded-N MMAs.
// MODE 0: (+bias if non-null) -> tf32 round -> C[m*ldc+n], n < nstore
// MODE 1: +bias -> tf32 round -> transposed store C[((b*NPA+n)*SEQ)+t]  (V^T)
// MODE 2: sigmoid(v*scale)    -> tf32 round -> C[m*ldc+n]
// MODE 3: +bias               -> fp32 exact -> C[m*ldc+n], n < nstore  (final out)
template <int MODE>
__global__ __launch_bounds__(128)
void gemm(const float* __restrict__ A, long long sA, int lda,
          const float* __restrict__ B, long long sB, int ldb,
          int kc, float* __restrict__ C, long long sC, int ldc,
          int nstore, int nmma, const float* __restrict__ bias, float scale)
{
    extern __shared__ __align__(16) float sm[];
    const int tid = threadIdx.x, wid = tid >> 5, lane = tid & 31;
    const int g = lane >> 2, t = lane & 3;
    const int bz = blockIdx.z, m0 = blockIdx.y * 128, n0 = blockIdx.x * 128;
    const int wm = (wid >> 1) * 64, wn = (wid & 1) * 64;

    // warp-uniform count of live 8-wide n-fragments in this warp's 64-col slab
    const int nrem = nmma - n0 - wn;
    const int nfmax = (nrem >= 64) ? 8 : ((nrem > 0) ? ((nrem + 7) >> 3) : 0);

    const float* Ab = A + bz * sA + (long long)m0 * lda;
    const float* Bb = B + bz * sB + (long long)n0 * ldb;
    const uint32_t sb = s2u(sm);

    auto load = [&](int ck, int buf) {
        const float* ag = Ab + ck * KC;
        const float* bg = Bb + ck * KC;
        uint32_t da = sb + (uint32_t)buf * (2 * TILE_F * 4);
        uint32_t db = da + TILE_F * 4;
        #pragma unroll
        for (int i = 0; i < 8; i++) {
            int e = tid + i * 128;               // 0..1023
            int r = e >> 3, c = e & 7;
            uint32_t off = (uint32_t)(r * (TSTRIDE * 4) + c * 16);
            cp16(da + off, ag + (long long)r * lda + c * 4);
            cp16(db + off, bg + (long long)r * ldb + c * 4);
        }
        asm volatile("cp.async.commit_group;" ::: "memory");
    };

    float acc[4][8][4] = {};
    uint32_t fa[2][4][4], fb[2][8][2];
    load(0, 0);

    for (int ck = 0; ck < kc; ++ck) {
        const int buf = ck & 1;
        if (ck + 1 < kc) {
            load(ck + 1, buf ^ 1);
            asm volatile("cp.async.wait_group 1;" ::: "memory");
        } else {
            asm volatile("cp.async.wait_group 0;" ::: "memory");
        }
        __syncthreads();

        const float* As = sm + buf * (2 * TILE_F);
        const float* Bs = As + TILE_F;

        // fragment loader for ks-step into pipeline slot pb
        auto ldfrag = [&](int ks, int pb) {
            const int k0 = ks * 8;
            #pragma unroll
            for (int mf = 0; mf < 4; mf++) {
                const int mr = wm + mf * 16 + g;
                fa[pb][mf][0] = __float_as_uint(As[mr * TSTRIDE + k0 + t]);
                fa[pb][mf][1] = __float_as_uint(As[(mr + 8) * TSTRIDE + k0 + t]);
                fa[pb][mf][2] = __float_as_uint(As[mr * TSTRIDE + k0 + t + 4]);
                fa[pb][mf][3] = __float_as_uint(As[(mr + 8) * TSTRIDE + k0 + t + 4]);
            }
            #pragma unroll
            for (int nf = 0; nf < 8; nf++) {
                if (nf < nfmax) {
                    const int nr = wn + nf * 8 + g;
                    fb[pb][nf][0] = __float_as_uint(Bs[nr * TSTRIDE + k0 + t]);
                    fb[pb][nf][1] = __float_as_uint(Bs[nr * TSTRIDE + k0 + t + 4]);
                }
            }
        };

        ldfrag(0, 0);
        #pragma unroll
        for (int ks = 0; ks < 4; ks++) {
            if (ks < 3) ldfrag(ks + 1, (ks + 1) & 1);
            const int pb = ks & 1;
            #pragma unroll
            for (int mf = 0; mf < 4; mf++)
                #pragma unroll
                for (int nf = 0; nf < 8; nf++)
                    if (nf < nfmax)
                        mma_tf32(acc[mf][nf], fa[pb][mf], fb[pb][nf]);
        }
        __syncthreads();
    }

    // ---- epilogue ----
    const int bi = (MODE == 1) ? (m0 / SEQ) : 0;
    const int tl0 = (MODE == 1) ? (m0 % SEQ) : 0;

    #pragma unroll
    for (int mf = 0; mf < 4; mf++) {
        #pragma unroll
        for (int half = 0; half < 2; half++) {
            const int mloc = wm + mf * 16 + g + half * 8;
            const int m = m0 + mloc;
            #pragma unroll
            for (int nf = 0; nf < 8; nf++) {
                const int n = n0 + wn + nf * 8 + 2 * t;
                if (n >= nstore) continue;
                float v0 = acc[mf][nf][half * 2 + 0];
                float v1 = acc[mf][nf][half * 2 + 1];
                if (MODE == 2) {
                    v0 = tf32r(1.0f / (1.0f + __expf(-v0 * scale)));
                    v1 = tf32r(1.0f / (1.0f + __expf(-v1 * scale)));
                } else if (MODE == 3) {
                    v0 += bias[n];
                    v1 += bias[n + 1 < NPA ? n + 1 : n];
                } else {
                    if (bias) { v0 += bias[n]; v1 += bias[n + 1 < NPA ? n + 1 : n]; }
                    v0 = tf32r(v0); v1 = tf32r(v1);
                }
                if (MODE == 1) {
                    const int tl = tl0 + mloc;
                    float* dst = C + ((long long)(bi * NPA + n)) * SEQ + tl;
                    dst[0] = v0;
                    if (n + 1 < nstore) dst[SEQ] = v1;
                } else if (MODE == 3) {
                    float* dst = C + bz * sC + (long long)m * ldc + n;
                    dst[0] = v0;
                    if (n + 1 < nstore) dst[1] = v1;
                } else {
                    float* dst = C + bz * sC + (long long)m * ldc + n;
                    *(float2*)dst = make_float2(v0, v1);   // nstore even, ldc even
                }
            }
        }
    }
}

// ---------------- host ----------------
extern "C" void kernel_launch(void* const* d_in, const int* in_sizes, int n_in,
                              void* d_out, int out_size)
{
    const float* q  = (const float*)d_in[0];
    const float* k  = (const float*)d_in[1];
    const float* v  = (const float*)d_in[2];
    const float* Wq = (const float*)d_in[3];
    const float* bq = (const float*)d_in[4];
    const float* Wk = (const float*)d_in[5];
    const float* bk = (const float*)d_in[6];
    const float* Wv = (const float*)d_in[7];
    const float* bv = (const float*)d_in[8];
    const float* Wo = (const float*)d_in[9];
    const float* bo = (const float*)d_in[10];
    float* out = (float*)d_out;

    float *x, *W, *bb, *qp, *kp, *vt, *s, *ct;
    cudaGetSymbolAddress((void**)&x,  g_x);
    cudaGetSymbolAddress((void**)&W,  g_W);
    cudaGetSymbolAddress((void**)&bb, g_b);
    cudaGetSymbolAddress((void**)&qp, g_qp);
    cudaGetSymbolAddress((void**)&kp, g_kp);
    cudaGetSymbolAddress((void**)&vt, g_vt);
    cudaGetSymbolAddress((void**)&s,  g_s);
    cudaGetSymbolAddress((void**)&ct, g_ct);

    cudaFuncSetAttribute(gemm<0>, cudaFuncAttributeMaxDynamicSharedMemorySize, SMEM_BYTES);
    cudaFuncSetAttribute(gemm<1>, cudaFuncAttributeMaxDynamicSharedMemorySize, SMEM_BYTES);
    cudaFuncSetAttribute(gemm<2>, cudaFuncAttributeMaxDynamicSharedMemorySize, SMEM_BYTES);
    cudaFuncSetAttribute(gemm<3>, cudaFuncAttributeMaxDynamicSharedMemorySize, SMEM_BYTES);

    const float scale = 1.0f / sqrtf((float)DIM);
    const size_t xs = (size_t)BT * KP, ws = (size_t)NPA * KP;

    prep_x<<<(BT * KP + 255) / 256, 256>>>(q, k, v);
    prep_w<<<(4 * NPA * KP + 255) / 256, 256>>>(Wq, bq, Wk, bk, Wv, bv, Wo, bo);

    // 1) projections: [BT,288] x [384,288]^T
    dim3 gp(3, BT / 128, 1);
    gemm<0><<<gp, 128, SMEM_BYTES>>>(x + 0 * xs, 0, KP, W + 0 * ws, 0, KP, KP / KC,
                                     qp, 0, KP, KP, DIM, bb + 0 * NPA, 0.f);
    gemm<0><<<gp, 128, SMEM_BYTES>>>(x + 1 * xs, 0, KP, W + 1 * ws, 0, KP, KP / KC,
                                     kp, 0, KP, KP, DIM, bb + 1 * NPA, 0.f);
    gemm<1><<<gp, 128, SMEM_BYTES>>>(x + 2 * xs, 0, KP, W + 2 * ws, 0, KP, KP / KC,
                                     vt, 0, KP, NPA, DIM, bb + 2 * NPA, 0.f);

    // 2) scores = sigmoid(qp @ kp^T * scale), per batch [2048,2048]
    dim3 gs(SEQ / 128, SEQ / 128, NB);
    gemm<2><<<gs, 128, SMEM_BYTES>>>(qp, (long long)SEQ * KP, KP,
                                     kp, (long long)SEQ * KP, KP, KP / KC,
                                     s, (long long)SEQ * SEQ, SEQ, SEQ, SEQ, nullptr, scale);

    // 3) ctx = scores @ V   (B = V^T [384, 2048] per batch, K = 2048)
    dim3 gc(3, SEQ / 128, NB);
    gemm<0><<<gc, 128, SMEM_BYTES>>>(s, (long long)SEQ * SEQ, SEQ,
                                     vt, (long long)NPA * SEQ, SEQ, SEQ / KC,
                                     ct, (long long)SEQ * KP, KP, KP, DIM, nullptr, 0.f);

    // 4) out = ctx @ Wo^T + bo  (fp32 exact store, [BT, 257])
    gemm<3><<<gp, 128, SMEM_BYTES>>>(ct, 0, KP, W + 3 * ws, 0, KP, KP / KC,
                                     out, 0, DIM, DIM, DIM, bb + 3 * NPA, 0.f);
}

// round 8
// speedup vs baseline: 1.2967x; 1.2967x over previous
#include <cuda_runtime.h>
#include <cuda_fp16.h>
#include <cstdint>
#include <math.h>

#define DIM 257
#define SEQ 2048
#define NB  8
#define BT  (NB * SEQ)        // 16384
#define KP  288               // padded K for dim-257 reductions (9 chunks of 32)
#define NPA 384               // padded N for B-operand buffers (3 full 128-tiles)
#define KC  32                // k halves per pipeline chunk
#define ASTR 40               // smem row stride in halves (80B; ldmatrix conflict-free)
#define TILE_B (128 * ASTR * 2)            // bytes per smem tile (10240)
#define SMEM_BYTES (2 * 2 * TILE_B)        // 40960

// ---------------- static device scratch (fp16 storage, fp32 accumulate) ----------------
__device__ __align__(16) __half g_x[3][(size_t)BT * KP];     // padded q,k,v
__device__ __align__(16) __half g_W[4][(size_t)NPA * KP];    // padded weights (K-major)
__device__ float g_b[4][NPA];                                // padded biases (fp32)
__device__ __align__(16) __half g_qp[(size_t)BT * KP];       // projected Q
__device__ __align__(16) __half g_kp[(size_t)BT * KP];       // projected K
__device__ __align__(16) __half g_vt[(size_t)NB * NPA * SEQ];// V projected, transposed [b][n][t]
__device__ __align__(16) __half g_s[(size_t)NB * SEQ * SEQ]; // sigmoid scores
__device__ __align__(16) __half g_ct[(size_t)BT * KP];       // context

// ---------------- helpers ----------------
__device__ __forceinline__ uint32_t s2u(const void* p) {
    uint32_t a;
    asm("{ .reg .u64 t; cvta.to.shared.u64 t, %1; cvt.u32.u64 %0, t; }" : "=r"(a) : "l"(p));
    return a;
}
__device__ __forceinline__ void cp16(uint32_t dst, const void* src) {
    asm volatile("cp.async.cg.shared.global [%0], [%1], 16;" :: "r"(dst), "l"(src));
}
#define LDMX4(r0, r1, r2, r3, addr) \
    asm volatile("ldmatrix.sync.aligned.m8n8.x4.shared.b16 {%0,%1,%2,%3}, [%4];" \
        : "=r"(r0), "=r"(r1), "=r"(r2), "=r"(r3) : "r"(addr))

__device__ __forceinline__ void mma_f16(float* d, const uint32_t* a, const uint32_t* b) {
    asm volatile(
        "mma.sync.aligned.m16n8k16.row.col.f32.f16.f16.f32 "
        "{%0,%1,%2,%3}, {%4,%5,%6,%7}, {%8,%9}, {%0,%1,%2,%3};"
        : "+f"(d[0]), "+f"(d[1]), "+f"(d[2]), "+f"(d[3])
        : "r"(a[0]), "r"(a[1]), "r"(a[2]), "r"(a[3]), "r"(b[0]), "r"(b[1]));
}

// ---------------- prep kernels (pad + fp16 round) ----------------
__global__ void prep_x(const float* __restrict__ q, const float* __restrict__ k,
                       const float* __restrict__ v) {
    int i = blockIdx.x * 256 + threadIdx.x;
    if (i >= BT * KP) return;
    int r = i / KP, c = i - r * KP;
    long long si = (long long)r * DIM + c;
    g_x[0][i] = (c < DIM) ? __float2half_rn(q[si]) : __half(0.f);
    g_x[1][i] = (c < DIM) ? __float2half_rn(k[si]) : __half(0.f);
    g_x[2][i] = (c < DIM) ? __float2half_rn(v[si]) : __half(0.f);
}
__global__ void prep_w(const float* W0, const float* b0, const float* W1, const float* b1,
                       const float* W2, const float* b2, const float* W3, const float* b3) {
    int i = blockIdx.x * 256 + threadIdx.x;
    const float* Ws[4] = {W0, W1, W2, W3};
    const float* bs[4] = {b0, b1, b2, b3};
    const int per = NPA * KP;
    if (i < 4 * per) {
        int w = i / per, rem = i - w * per, r = rem / KP, c = rem - r * KP;
        g_W[w][(size_t)r * KP + c] =
            (r < DIM && c < DIM) ? __float2half_rn(Ws[w][r * DIM + c]) : __half(0.f);
    }
    if (i < 4 * NPA) {
        int w = i / NPA, n = i - w * NPA;
        g_b[w][n] = (n < DIM) ? bs[w][n] : 0.f;
    }
}

// ---------------- fp16 tensor-core GEMM: D[m,n] = sum_k A[m,k]*B[n,k] ----------------
// 128x128 CTA tile, 4 warps, 64x64 warp tile. ldmatrix fragment loads, m16n8k16 MMA.
// Runtime nf-mask (nmma) skips padded-N MMAs.
// MODE 0: (+bias if non-null) -> fp16 -> C[m*ldc+n], n < nstore
// MODE 1: +bias -> fp16 -> transposed store C[((b*NPA+n)*SEQ)+t]  (V^T)
// MODE 2: sigmoid(v*scale) -> fp16 -> C[m*ldc+n]
// MODE 3: +bias -> fp32 exact -> Cf[m*ldc+n], n < nstore  (final out)
template <int MODE>
__global__ __launch_bounds__(128)
void gemm(const __half* __restrict__ A, long long sA, int lda,
          const __half* __restrict__ B, long long sB, int ldb,
          int kc, __half* __restrict__ C, float* __restrict__ Cf,
          long long sC, int ldc,
          int nstore, int nmma, const float* __restrict__ bias, float scale)
{
    extern __shared__ __align__(16) char sm[];
    const int tid = threadIdx.x, wid = tid >> 5, lane = tid & 31;
    const int g = lane >> 2, t = lane & 3;
    const int lrow = lane & 7, seg = lane >> 3;
    const int bz = blockIdx.z, m0 = blockIdx.y * 128, n0 = blockIdx.x * 128;
    const int wm = (wid >> 1) * 64, wn = (wid & 1) * 64;

    // warp-uniform count of live 8-wide n-fragments in this warp's 64-col slab
    const int nrem = nmma - n0 - wn;
    const int nfmax = (nrem >= 64) ? 8 : ((nrem > 0) ? ((nrem + 7) >> 3) : 0);

    const __half* Ab = A + bz * sA + (long long)m0 * lda;
    const __half* Bb = B + bz * sB + (long long)n0 * ldb;
    const uint32_t sb = s2u(sm);

    auto load = [&](int ck, int buf) {
        const char* ag = (const char*)(Ab + ck * KC);
        const char* bg = (const char*)(Bb + ck * KC);
        uint32_t da = sb + (uint32_t)buf * (2 * TILE_B);
        uint32_t db = da + TILE_B;
        #pragma unroll
        for (int i = 0; i < 4; i++) {
            int e = tid + i * 128;               // 0..511
            int r = e >> 2, c = e & 3;
            uint32_t off = (uint32_t)(r * (ASTR * 2) + c * 16);
            cp16(da + off, ag + (long long)r * lda * 2 + c * 16);
            cp16(db + off, bg + (long long)r * ldb * 2 + c * 16);
        }
        asm volatile("cp.async.commit_group;" ::: "memory");
    };

    // per-thread ldmatrix base offsets (bytes within a tile)
    // A mf fragment: rows wm+mf*16+lrow+(seg&1)*8, k-halves offset (seg>>1)*8
    const uint32_t aoff = (uint32_t)((wm + lrow + (seg & 1) * 8) * (ASTR * 2) + (seg >> 1) * 16);
    // B pair j (nf=2j,2j+1): rows wn+j*16+lrow+(seg>>1)*8, k-halves offset (seg&1)*8
    const uint32_t boff = (uint32_t)((wn + lrow + (seg >> 1) * 8) * (ASTR * 2) + (seg & 1) * 16);

    float acc[4][8][4] = {};
    load(0, 0);

    for (int ck = 0; ck < kc; ++ck) {
        const int buf = ck & 1;
        if (ck + 1 < kc) {
            load(ck + 1, buf ^ 1);
            asm volatile("cp.async.wait_group 1;" ::: "memory");
        } else {
            asm volatile("cp.async.wait_group 0;" ::: "memory");
        }
        __syncthreads();

        const uint32_t ta = sb + (uint32_t)buf * (2 * TILE_B);
        const uint32_t tb = ta + TILE_B;

        #pragma unroll
        for (int ks = 0; ks < 2; ks++) {        // two k16 steps per 32-half chunk
            const uint32_t kbyte = (uint32_t)(ks * 32);
            uint32_t fa[4][4], fb[8][2];
            #pragma unroll
            for (int mf = 0; mf < 4; mf++) {
                LDMX4(fa[mf][0], fa[mf][1], fa[mf][2], fa[mf][3],
                      ta + aoff + (uint32_t)mf * (16 * ASTR * 2) + kbyte);
            }
            #pragma unroll
            for (int j = 0; j < 4; j++) {
                if (2 * j < nfmax) {
                    uint32_t r0, r1, r2, r3;
                    LDMX4(r0, r1, r2, r3,
                          tb + boff + (uint32_t)j * (16 * ASTR * 2) + kbyte);
                    fb[2 * j][0] = r0; fb[2 * j][1] = r1;
                    fb[2 * j + 1][0] = r2; fb[2 * j + 1][1] = r3;
                }
            }
            #pragma unroll
            for (int mf = 0; mf < 4; mf++)
                #pragma unroll
                for (int nf = 0; nf < 8; nf++)
                    if (nf < nfmax)
                        mma_f16(acc[mf][nf], fa[mf], fb[nf]);
        }
        __syncthreads();
    }

    // ---- epilogue ----
    const int bi = (MODE == 1) ? (m0 / SEQ) : 0;
    const int tl0 = (MODE == 1) ? (m0 % SEQ) : 0;

    #pragma unroll
    for (int mf = 0; mf < 4; mf++) {
        #pragma unroll
        for (int half = 0; half < 2; half++) {
            const int mloc = wm + mf * 16 + g + half * 8;
            const int m = m0 + mloc;
            #pragma unroll
            for (int nf = 0; nf < 8; nf++) {
                const int n = n0 + wn + nf * 8 + 2 * t;
                if (n >= nstore) continue;
                float v0 = acc[mf][nf][half * 2 + 0];
                float v1 = acc[mf][nf][half * 2 + 1];
                if (MODE == 2) {
                    v0 = 1.0f / (1.0f + __expf(-v0 * scale));
                    v1 = 1.0f / (1.0f + __expf(-v1 * scale));
                } else if (MODE == 3) {
                    v0 += bias[n];
                    v1 += bias[n + 1 < NPA ? n + 1 : n];
                } else {
                    if (bias) { v0 += bias[n]; v1 += bias[n + 1 < NPA ? n + 1 : n]; }
                }
                if (MODE == 1) {
                    const int tl = tl0 + mloc;
                    __half* dst = C + ((long long)(bi * NPA + n)) * SEQ + tl;
                    dst[0] = __float2half_rn(v0);
                    if (n + 1 < nstore) dst[SEQ] = __float2half_rn(v1);
                } else if (MODE == 3) {
                    float* dst = Cf + bz * sC + (long long)m * ldc + n;
                    dst[0] = v0;
                    if (n + 1 < nstore) dst[1] = v1;
                } else {
                    __half* dst = C + bz * sC + (long long)m * ldc + n;
                    __half2 h2;
                    h2.x = __float2half_rn(v0);
                    h2.y = __float2half_rn(v1);
                    *(__half2*)dst = h2;                 // n even, ldc even
                }
            }
        }
    }
}

// ---------------- host ----------------
extern "C" void kernel_launch(void* const* d_in, const int* in_sizes, int n_in,
                              void* d_out, int out_size)
{
    const float* q  = (const float*)d_in[0];
    const float* k  = (const float*)d_in[1];
    const float* v  = (const float*)d_in[2];
    const float* Wq = (const float*)d_in[3];
    const float* bq = (const float*)d_in[4];
    const float* Wk = (const float*)d_in[5];
    const float* bk = (const float*)d_in[6];
    const float* Wv = (const float*)d_in[7];
    const float* bv = (const float*)d_in[8];
    const float* Wo = (const float*)d_in[9];
    const float* bo = (const float*)d_in[10];
    float* out = (float*)d_out;

    __half *x, *W, *qp, *kp, *vt, *s, *ct;
    float* bb;
    cudaGetSymbolAddress((void**)&x,  g_x);
    cudaGetSymbolAddress((void**)&W,  g_W);
    cudaGetSymbolAddress((void**)&bb, g_b);
    cudaGetSymbolAddress((void**)&qp, g_qp);
    cudaGetSymbolAddress((void**)&kp, g_kp);
    cudaGetSymbolAddress((void**)&vt, g_vt);
    cudaGetSymbolAddress((void**)&s,  g_s);
    cudaGetSymbolAddress((void**)&ct, g_ct);

    cudaFuncSetAttribute(gemm<0>, cudaFuncAttributeMaxDynamicSharedMemorySize, SMEM_BYTES);
    cudaFuncSetAttribute(gemm<1>, cudaFuncAttributeMaxDynamicSharedMemorySize, SMEM_BYTES);
    cudaFuncSetAttribute(gemm<2>, cudaFuncAttributeMaxDynamicSharedMemorySize, SMEM_BYTES);
    cudaFuncSetAttribute(gemm<3>, cudaFuncAttributeMaxDynamicSharedMemorySize, SMEM_BYTES);

    const float scale = 1.0f / sqrtf((float)DIM);
    const size_t xs = (size_t)BT * KP, ws = (size_t)NPA * KP;

    prep_x<<<(BT * KP + 255) / 256, 256>>>(q, k, v);
    prep_w<<<(4 * NPA * KP + 255) / 256, 256>>>(Wq, bq, Wk, bk, Wv, bv, Wo, bo);

    // 1) projections: [BT,288] x [384,288]^T
    dim3 gp(3, BT / 128, 1);
    gemm<0><<<gp, 128, SMEM_BYTES>>>(x + 0 * xs, 0, KP, W + 0 * ws, 0, KP, KP / KC,
                                     qp, nullptr, 0, KP, KP, DIM, bb + 0 * NPA, 0.f);
    gemm<0><<<gp, 128, SMEM_BYTES>>>(x + 1 * xs, 0, KP, W + 1 * ws, 0, KP, KP / KC,
                                     kp, nullptr, 0, KP, KP, DIM, bb + 1 * NPA, 0.f);
    gemm<1><<<gp, 128, SMEM_BYTES>>>(x + 2 * xs, 0, KP, W + 2 * ws, 0, KP, KP / KC,
                                     vt, nullptr, 0, KP, NPA, DIM, bb + 2 * NPA, 0.f);

    // 2) scores = sigmoid(qp @ kp^T * scale), per batch [2048,2048]
    dim3 gs(SEQ / 128, SEQ / 128, NB);
    gemm<2><<<gs, 128, SMEM_BYTES>>>(qp, (long long)SEQ * KP, KP,
                                     kp, (long long)SEQ * KP, KP, KP / KC,
                                     s, nullptr, (long long)SEQ * SEQ, SEQ, SEQ, SEQ,
                                     nullptr, scale);

    // 3) ctx = scores @ V   (B = V^T [384, 2048] per batch, K = 2048)
    dim3 gc(3, SEQ / 128, NB);
    gemm<0><<<gc, 128, SMEM_BYTES>>>(s, (long long)SEQ * SEQ, SEQ,
                                     vt, (long long)NPA * SEQ, SEQ, SEQ / KC,
                                     ct, nullptr, (long long)SEQ * KP, KP, KP, DIM,
                                     nullptr, 0.f);

    // 4) out = ctx @ Wo^T + bo  (fp32 exact store, [BT, 257])
    gemm<3><<<gp, 128, SMEM_BYTES>>>(ct, 0, KP, W + 3 * ws, 0, KP, KP / KC,
                                     nullptr, out, 0, DIM, DIM, DIM, bb + 3 * NPA, 0.f);
}

// round 9
// speedup vs baseline: 1.3840x; 1.0673x over previous
#include <cuda_runtime.h>
#include <cuda_fp16.h>
#include <cstdint>
#include <math.h>

#define DIM 257
#define SEQ 2048
#define NB  8
#define BT  (NB * SEQ)        // 16384
#define KP  320               // padded K (5 chunks of 64)
#define NPA 384               // padded N for B-operand buffers
#define KC  64                // k halves per pipeline chunk (128B rows)
#define ASTR 72               // smem row stride in halves (144B; ldmatrix conflict-free)
#define TILE_B (128 * ASTR * 2)            // bytes per smem tile (18432)
#define SMEM_BYTES (2 * 2 * TILE_B)        // 73728

// ---------------- static device scratch (fp16 storage, fp32 accumulate) ----------------
__device__ __align__(16) __half g_x[3][(size_t)BT * KP];     // padded q,k,v
__device__ __align__(16) __half g_W[4][(size_t)NPA * KP];    // padded weights (K-major)
__device__ float g_b[4][NPA];                                // padded biases (fp32)
__device__ __align__(16) __half g_qp[(size_t)BT * KP];       // projected Q
__device__ __align__(16) __half g_kp[(size_t)BT * KP];       // projected K
__device__ __align__(16) __half g_vt[(size_t)NB * NPA * SEQ];// V projected, transposed [b][n][t]
__device__ __align__(16) __half g_s[(size_t)NB * SEQ * SEQ]; // sigmoid scores
__device__ __align__(16) __half g_ct[(size_t)BT * KP];       // context

// ---------------- helpers ----------------
__device__ __forceinline__ uint32_t s2u(const void* p) {
    uint32_t a;
    asm("{ .reg .u64 t; cvta.to.shared.u64 t, %1; cvt.u32.u64 %0, t; }" : "=r"(a) : "l"(p));
    return a;
}
__device__ __forceinline__ void cp16(uint32_t dst, const void* src) {
    asm volatile("cp.async.cg.shared.global [%0], [%1], 16;" :: "r"(dst), "l"(src));
}
#define LDMX4(r0, r1, r2, r3, addr) \
    asm volatile("ldmatrix.sync.aligned.m8n8.x4.shared.b16 {%0,%1,%2,%3}, [%4];" \
        : "=r"(r0), "=r"(r1), "=r"(r2), "=r"(r3) : "r"(addr))

__device__ __forceinline__ void mma_f16(float* d, const uint32_t* a, const uint32_t* b) {
    asm volatile(
        "mma.sync.aligned.m16n8k16.row.col.f32.f16.f16.f32 "
        "{%0,%1,%2,%3}, {%4,%5,%6,%7}, {%8,%9}, {%0,%1,%2,%3};"
        : "+f"(d[0]), "+f"(d[1]), "+f"(d[2]), "+f"(d[3])
        : "r"(a[0]), "r"(a[1]), "r"(a[2]), "r"(a[3]), "r"(b[0]), "r"(b[1]));
}

// ---------------- prep kernels (pad + fp16 round) ----------------
__global__ void prep_x(const float* __restrict__ q, const float* __restrict__ k,
                       const float* __restrict__ v) {
    int i = blockIdx.x * 256 + threadIdx.x;
    if (i >= BT * KP) return;
    int r = i / KP, c = i - r * KP;
    long long si = (long long)r * DIM + c;
    g_x[0][i] = (c < DIM) ? __float2half_rn(q[si]) : __float2half_rn(0.f);
    g_x[1][i] = (c < DIM) ? __float2half_rn(k[si]) : __float2half_rn(0.f);
    g_x[2][i] = (c < DIM) ? __float2half_rn(v[si]) : __float2half_rn(0.f);
}
__global__ void prep_w(const float* W0, const float* b0, const float* W1, const float* b1,
                       const float* W2, const float* b2, const float* W3, const float* b3) {
    int i = blockIdx.x * 256 + threadIdx.x;
    const float* Ws[4] = {W0, W1, W2, W3};
    const float* bs[4] = {b0, b1, b2, b3};
    const int per = NPA * KP;
    if (i < 4 * per) {
        int w = i / per, rem = i - w * per, r = rem / KP, c = rem - r * KP;
        g_W[w][(size_t)r * KP + c] =
            (r < DIM && c < DIM) ? __float2half_rn(Ws[w][r * DIM + c]) : __float2half_rn(0.f);
    }
    if (i < 4 * NPA) {
        int w = i / NPA, n = i - w * NPA;
        g_b[w][n] = (n < DIM) ? bs[w][n] : 0.f;
    }
}

// ---------------- fp16 tensor-core GEMM: D[m,n] = sum_k A[m,k]*B[n,k] ----------------
// 128x128 CTA tile, 4 warps, 64x64 warp tile. ldmatrix fragments, m16n8k16 MMA.
// Runtime nf-mask (nmma) skips padded-N MMAs.
// MODE 0: (+bias if non-null) -> fp16 -> C[m*ldc+n], n < nstore
// MODE 2: sigmoid(v*scale) -> fp16 -> C[m*ldc+n]
// MODE 3: +bias -> fp32 exact -> Cf[m*ldc+n], n < nstore  (final out)
// MODE 4: fused QKV: bz selects input/weight/bias from globals; bz<2 -> qp/kp
//         normal store (nstore=KP); bz==2 -> transposed V^T store (nstore=NPA)
template <int MODE>
__global__ __launch_bounds__(128)
void gemm(const __half* __restrict__ A, long long sA, int lda,
          const __half* __restrict__ B, long long sB, int ldb,
          int kc, __half* __restrict__ C, float* __restrict__ Cf,
          long long sC, int ldc,
          int nstore, int nmma, const float* __restrict__ bias, float scale)
{
    extern __shared__ __align__(16) char sm[];
    const int tid = threadIdx.x, wid = tid >> 5, lane = tid & 31;
    const int g = lane >> 2, t = lane & 3;
    const int lrow = lane & 7, seg = lane >> 3;
    const int bz = blockIdx.z, m0 = blockIdx.y * 128, n0 = blockIdx.x * 128;
    const int wm = (wid >> 1) * 64, wn = (wid & 1) * 64;

    if (MODE == 4) {
        A = g_x[bz]; B = g_W[bz]; bias = g_b[bz];
        nstore = (bz == 2) ? NPA : KP;
    }

    // warp-uniform count of live 8-wide n-fragments in this warp's 64-col slab
    const int nrem = nmma - n0 - wn;
    const int nfmax = (nrem >= 64) ? 8 : ((nrem > 0) ? ((nrem + 7) >> 3) : 0);

    const __half* Ab = A + (MODE == 4 ? 0 : bz * sA) + (long long)m0 * lda;
    const __half* Bb = B + (MODE == 4 ? 0 : bz * sB) + (long long)n0 * ldb;
    const uint32_t sb = s2u(sm);

    auto load = [&](int ck, int buf) {
        const char* ag = (const char*)(Ab + ck * KC);
        const char* bg = (const char*)(Bb + ck * KC);
        uint32_t da = sb + (uint32_t)buf * (2 * TILE_B);
        uint32_t db = da + TILE_B;
        #pragma unroll
        for (int i = 0; i < 8; i++) {
            int e = tid + i * 128;               // 0..1023
            int r = e >> 3, c = e & 7;
            uint32_t off = (uint32_t)(r * (ASTR * 2) + c * 16);
            cp16(da + off, ag + (long long)r * lda * 2 + c * 16);
            cp16(db + off, bg + (long long)r * ldb * 2 + c * 16);
        }
        asm volatile("cp.async.commit_group;" ::: "memory");
    };

    // per-thread ldmatrix base offsets (bytes within a tile)
    const uint32_t aoff = (uint32_t)((wm + lrow + (seg & 1) * 8) * (ASTR * 2) + (seg >> 1) * 16);
    const uint32_t boff = (uint32_t)((wn + lrow + (seg >> 1) * 8) * (ASTR * 2) + (seg & 1) * 16);

    float acc[4][8][4] = {};
    load(0, 0);

    for (int ck = 0; ck < kc; ++ck) {
        const int buf = ck & 1;
        if (ck + 1 < kc) {
            load(ck + 1, buf ^ 1);
            asm volatile("cp.async.wait_group 1;" ::: "memory");
        } else {
            asm volatile("cp.async.wait_group 0;" ::: "memory");
        }
        __syncthreads();

        const uint32_t ta = sb + (uint32_t)buf * (2 * TILE_B);
        const uint32_t tb = ta + TILE_B;

        #pragma unroll
        for (int ks = 0; ks < 4; ks++) {        // four k16 steps per 64-half chunk
            const uint32_t kbyte = (uint32_t)(ks * 32);
            uint32_t fa[4][4], fb[8][2];
            #pragma unroll
            for (int mf = 0; mf < 4; mf++) {
                LDMX4(fa[mf][0], fa[mf][1], fa[mf][2], fa[mf][3],
                      ta + aoff + (uint32_t)mf * (16 * ASTR * 2) + kbyte);
            }
            #pragma unroll
            for (int j = 0; j < 4; j++) {
                if (2 * j < nfmax) {
                    uint32_t r0, r1, r2, r3;
                    LDMX4(r0, r1, r2, r3,
                          tb + boff + (uint32_t)j * (16 * ASTR * 2) + kbyte);
                    fb[2 * j][0] = r0; fb[2 * j][1] = r1;
                    fb[2 * j + 1][0] = r2; fb[2 * j + 1][1] = r3;
                }
            }
            #pragma unroll
            for (int mf = 0; mf < 4; mf++)
                #pragma unroll
                for (int nf = 0; nf < 8; nf++)
                    if (nf < nfmax)
                        mma_f16(acc[mf][nf], fa[mf], fb[nf]);
        }
        __syncthreads();
    }

    // ---- epilogue ----
    const bool vtrans = (MODE == 4) && (bz == 2);
    const int bi = m0 / SEQ;
    const int tl0 = m0 % SEQ;

    #pragma unroll
    for (int mf = 0; mf < 4; mf++) {
        #pragma unroll
        for (int half = 0; half < 2; half++) {
            const int mloc = wm + mf * 16 + g + half * 8;
            const int m = m0 + mloc;
            #pragma unroll
            for (int nf = 0; nf < 8; nf++) {
                const int n = n0 + wn + nf * 8 + 2 * t;
                if (n >= nstore) continue;
                float v0 = acc[mf][nf][half * 2 + 0];
                float v1 = acc[mf][nf][half * 2 + 1];
                if (MODE == 2) {
                    v0 = 1.0f / (1.0f + __expf(-v0 * scale));
                    v1 = 1.0f / (1.0f + __expf(-v1 * scale));
                } else {
                    if (bias) { v0 += bias[n]; v1 += bias[n + 1 < NPA ? n + 1 : n]; }
                }
                if (MODE == 4) {
                    if (vtrans) {
                        const int tl = tl0 + mloc;
                        __half* dst = g_vt + ((long long)(bi * NPA + n)) * SEQ + tl;
                        dst[0] = __float2half_rn(v0);
                        if (n + 1 < nstore) dst[SEQ] = __float2half_rn(v1);
                    } else {
                        __half* dst = (bz ? g_kp : g_qp) + (long long)m * KP + n;
                        __half2 h2;
                        h2.x = __float2half_rn(v0);
                        h2.y = __float2half_rn(v1);
                        *(__half2*)dst = h2;
                    }
                } else if (MODE == 3) {
                    float* dst = Cf + bz * sC + (long long)m * ldc + n;
                    dst[0] = v0;
                    if (n + 1 < nstore) dst[1] = v1;
                } else {
                    __half* dst = C + bz * sC + (long long)m * ldc + n;
                    __half2 h2;
                    h2.x = __float2half_rn(v0);
                    h2.y = __float2half_rn(v1);
                    *(__half2*)dst = h2;                 // n even, ldc even
                }
            }
        }
    }
}

// ---------------- host ----------------
extern "C" void kernel_launch(void* const* d_in, const int* in_sizes, int n_in,
                              void* d_out, int out_size)
{
    const float* q  = (const float*)d_in[0];
    const float* k  = (const float*)d_in[1];
    const float* v  = (const float*)d_in[2];
    const float* Wq = (const float*)d_in[3];
    const float* bq = (const float*)d_in[4];
    const float* Wk = (const float*)d_in[5];
    const float* bk = (const float*)d_in[6];
    const float* Wv = (const float*)d_in[7];
    const float* bv = (const float*)d_in[8];
    const float* Wo = (const float*)d_in[9];
    const float* bo = (const float*)d_in[10];
    float* out = (float*)d_out;

    __half *W, *qp, *kp, *vt, *s, *ct;
    float* bb;
    cudaGetSymbolAddress((void**)&W,  g_W);
    cudaGetSymbolAddress((void**)&bb, g_b);
    cudaGetSymbolAddress((void**)&qp, g_qp);
    cudaGetSymbolAddress((void**)&kp, g_kp);
    cudaGetSymbolAddress((void**)&vt, g_vt);
    cudaGetSymbolAddress((void**)&s,  g_s);
    cudaGetSymbolAddress((void**)&ct, g_ct);

    cudaFuncSetAttribute(gemm<0>, cudaFuncAttributeMaxDynamicSharedMemorySize, SMEM_BYTES);
    cudaFuncSetAttribute(gemm<2>, cudaFuncAttributeMaxDynamicSharedMemorySize, SMEM_BYTES);
    cudaFuncSetAttribute(gemm<3>, cudaFuncAttributeMaxDynamicSharedMemorySize, SMEM_BYTES);
    cudaFuncSetAttribute(gemm<4>, cudaFuncAttributeMaxDynamicSharedMemorySize, SMEM_BYTES);

    const float scale = 1.0f / sqrtf((float)DIM);
    const size_t ws = (size_t)NPA * KP;

    prep_x<<<(BT * KP + 255) / 256, 256>>>(q, k, v);
    prep_w<<<(4 * NPA * KP + 255) / 256, 256>>>(Wq, bq, Wk, bk, Wv, bv, Wo, bo);

    // 1) fused QKV projections: grid.z selects input (0=q,1=k,2=v->V^T)
    dim3 gf(3, BT / 128, 3);
    gemm<4><<<gf, 128, SMEM_BYTES>>>(nullptr, 0, KP, nullptr, 0, KP, KP / KC,
                                     nullptr, nullptr, 0, KP, 0, DIM, nullptr, 0.f);

    // 2) scores = sigmoid(qp @ kp^T * scale), per batch [2048,2048]
    dim3 gs(SEQ / 128, SEQ / 128, NB);
    gemm<2><<<gs, 128, SMEM_BYTES>>>(qp, (long long)SEQ * KP, KP,
                                     kp, (long long)SEQ * KP, KP, KP / KC,
                                     s, nullptr, (long long)SEQ * SEQ, SEQ, SEQ, SEQ,
                                     nullptr, scale);

    // 3) ctx = scores @ V   (B = V^T [384, 2048] per batch, K = 2048)
    dim3 gc(3, SEQ / 128, NB);
    gemm<0><<<gc, 128, SMEM_BYTES>>>(s, (long long)SEQ * SEQ, SEQ,
                                     vt, (long long)NPA * SEQ, SEQ, SEQ / KC,
                                     ct, nullptr, (long long)SEQ * KP, KP, KP, DIM,
                                     nullptr, 0.f);

    // 4) out = ctx @ Wo^T + bo  (fp32 exact store, [BT, 257])
    dim3 gp(3, BT / 128, 1);
    gemm<3><<<gp, 128, SMEM_BYTES>>>(ct, 0, KP, W + 3 * ws, 0, KP, KP / KC,
                                     nullptr, out, 0, DIM, DIM, DIM, bb + 3 * NPA, 0.f);
}

// round 10
// speedup vs baseline: 1.8482x; 1.3354x over previous
#include <cuda_runtime.h>
#include <cuda_fp16.h>
#include <cstdint>
#include <math.h>

#define DIM 257
#define SEQ 2048
#define NB  8
#define BT  (NB * SEQ)        // 16384
#define KP  320               // padded K (5 chunks of 64)
#define NPA 384               // padded N for B-operand buffers
#define KC  64                // k halves per pipeline chunk (128B rows)
#define ASTR 72               // smem row stride in halves (144B; ldmatrix conflict-free)
#define TILE_B (128 * ASTR * 2)            // bytes per smem tile (18432)
#define SMEM_BYTES (2 * 2 * TILE_B)        // 73728

// ---------------- static device scratch (fp16 storage, fp32 accumulate) ----------------
__device__ __align__(16) __half g_x[3][(size_t)BT * KP];     // padded q,k,v
__device__ __align__(16) __half g_W[4][(size_t)NPA * KP];    // padded weights (K-major)
__device__ float g_b[4][NPA];                                // padded biases (fp32)
__device__ __align__(16) __half g_qp[(size_t)BT * KP];       // projected Q
__device__ __align__(16) __half g_kp[(size_t)BT * KP];       // projected K
__device__ __align__(16) __half g_vt[(size_t)NB * NPA * SEQ];// V projected, transposed [b][n][t]
__device__ __align__(16) __half g_s[(size_t)NB * SEQ * SEQ]; // sigmoid scores
__device__ __align__(16) __half g_ct[(size_t)BT * KP];       // context

// ---------------- helpers ----------------
__device__ __forceinline__ uint32_t s2u(const void* p) {
    uint32_t a;
    asm("{ .reg .u64 t; cvta.to.shared.u64 t, %1; cvt.u32.u64 %0, t; }" : "=r"(a) : "l"(p));
    return a;
}
__device__ __forceinline__ void cp16(uint32_t dst, const void* src) {
    asm volatile("cp.async.cg.shared.global [%0], [%1], 16;" :: "r"(dst), "l"(src));
}
#define LDMX4(r0, r1, r2, r3, addr) \
    asm volatile("ldmatrix.sync.aligned.m8n8.x4.shared.b16 {%0,%1,%2,%3}, [%4];" \
        : "=r"(r0), "=r"(r1), "=r"(r2), "=r"(r3) : "r"(addr))

__device__ __forceinline__ void mma_f16(float* d, const uint32_t* a, const uint32_t* b) {
    asm volatile(
        "mma.sync.aligned.m16n8k16.row.col.f32.f16.f16.f32 "
        "{%0,%1,%2,%3}, {%4,%5,%6,%7}, {%8,%9}, {%0,%1,%2,%3};"
        : "+f"(d[0]), "+f"(d[1]), "+f"(d[2]), "+f"(d[3])
        : "r"(a[0]), "r"(a[1]), "r"(a[2]), "r"(a[3]), "r"(b[0]), "r"(b[1]));
}

// ---------------- prep kernels (pad + fp16 round) ----------------
__global__ void prep_x(const float* __restrict__ q, const float* __restrict__ k,
                       const float* __restrict__ v) {
    int i = blockIdx.x * 256 + threadIdx.x;
    if (i >= BT * KP) return;
    int r = i / KP, c = i - r * KP;
    long long si = (long long)r * DIM + c;
    g_x[0][i] = (c < DIM) ? __float2half_rn(q[si]) : __float2half_rn(0.f);
    g_x[1][i] = (c < DIM) ? __float2half_rn(k[si]) : __float2half_rn(0.f);
    g_x[2][i] = (c < DIM) ? __float2half_rn(v[si]) : __float2half_rn(0.f);
}
__global__ void prep_w(const float* W0, const float* b0, const float* W1, const float* b1,
                       const float* W2, const float* b2, const float* W3, const float* b3) {
    int i = blockIdx.x * 256 + threadIdx.x;
    const float* Ws[4] = {W0, W1, W2, W3};
    const float* bs[4] = {b0, b1, b2, b3};
    const int per = NPA * KP;
    if (i < 4 * per) {
        int w = i / per, rem = i - w * per, r = rem / KP, c = rem - r * KP;
        g_W[w][(size_t)r * KP + c] =
            (r < DIM && c < DIM) ? __float2half_rn(Ws[w][r * DIM + c]) : __float2half_rn(0.f);
    }
    if (i < 4 * NPA) {
        int w = i / NPA, n = i - w * NPA;
        g_b[w][n] = (n < DIM) ? bs[w][n] : 0.f;
    }
}

// ---------------- fp16 tensor-core GEMM: D[m,n] = sum_k A[m,k]*B[n,k] ----------------
// 128x128 CTA tile, 8 warps (256 thr), 32x64 warp tile (4x2 warp grid).
// ldmatrix fragments, m16n8k16 MMA. Runtime nf-mask (nmma) skips padded-N MMAs.
// MODE 0: (+bias if non-null) -> fp16 -> C[m*ldc+n], n < nstore
// MODE 2: sigmoid(v*scale) -> fp16 -> C[m*ldc+n]
// MODE 3: +bias -> fp32 exact -> Cf[m*ldc+n], n < nstore  (final out)
// MODE 4: fused QKV: bz selects input/weight/bias from globals; bz<2 -> qp/kp
//         normal store (nstore=KP); bz==2 -> transposed V^T store (nstore=NPA)
template <int MODE>
__global__ __launch_bounds__(256, 2)
void gemm(const __half* __restrict__ A, long long sA, int lda,
          const __half* __restrict__ B, long long sB, int ldb,
          int kc, __half* __restrict__ C, float* __restrict__ Cf,
          long long sC, int ldc,
          int nstore, int nmma, const float* __restrict__ bias, float scale)
{
    extern __shared__ __align__(16) char sm[];
    const int tid = threadIdx.x, wid = tid >> 5, lane = tid & 31;
    const int g = lane >> 2, t = lane & 3;
    const int lrow = lane & 7, seg = lane >> 3;
    const int bz = blockIdx.z, m0 = blockIdx.y * 128, n0 = blockIdx.x * 128;
    const int wm = (wid >> 1) * 32, wn = (wid & 1) * 64;

    if (MODE == 4) {
        A = g_x[bz]; B = g_W[bz]; bias = g_b[bz];
        nstore = (bz == 2) ? NPA : KP;
    }

    // warp-uniform count of live 8-wide n-fragments in this warp's 64-col slab
    const int nrem = nmma - n0 - wn;
    const int nfmax = (nrem >= 64) ? 8 : ((nrem > 0) ? ((nrem + 7) >> 3) : 0);

    const __half* Ab = A + (MODE == 4 ? 0 : bz * sA) + (long long)m0 * lda;
    const __half* Bb = B + (MODE == 4 ? 0 : bz * sB) + (long long)n0 * ldb;
    const uint32_t sb = s2u(sm);

    auto load = [&](int ck, int buf) {
        const char* ag = (const char*)(Ab + ck * KC);
        const char* bg = (const char*)(Bb + ck * KC);
        uint32_t da = sb + (uint32_t)buf * (2 * TILE_B);
        uint32_t db = da + TILE_B;
        #pragma unroll
        for (int i = 0; i < 4; i++) {
            int e = tid + i * 256;               // 0..1023
            int r = e >> 3, c = e & 7;
            uint32_t off = (uint32_t)(r * (ASTR * 2) + c * 16);
            cp16(da + off, ag + (long long)r * lda * 2 + c * 16);
            cp16(db + off, bg + (long long)r * ldb * 2 + c * 16);
        }
        asm volatile("cp.async.commit_group;" ::: "memory");
    };

    // per-thread ldmatrix base offsets (bytes within a tile)
    const uint32_t aoff = (uint32_t)((wm + lrow + (seg & 1) * 8) * (ASTR * 2) + (seg >> 1) * 16);
    const uint32_t boff = (uint32_t)((wn + lrow + (seg >> 1) * 8) * (ASTR * 2) + (seg & 1) * 16);

    float acc[2][8][4] = {};
    load(0, 0);

    for (int ck = 0; ck < kc; ++ck) {
        const int buf = ck & 1;
        if (ck + 1 < kc) {
            load(ck + 1, buf ^ 1);
            asm volatile("cp.async.wait_group 1;" ::: "memory");
        } else {
            asm volatile("cp.async.wait_group 0;" ::: "memory");
        }
        __syncthreads();

        const uint32_t ta = sb + (uint32_t)buf * (2 * TILE_B);
        const uint32_t tb = ta + TILE_B;

        #pragma unroll
        for (int ks = 0; ks < 4; ks++) {        // four k16 steps per 64-half chunk
            const uint32_t kbyte = (uint32_t)(ks * 32);
            uint32_t fa[2][4], fb[8][2];
            #pragma unroll
            for (int mf = 0; mf < 2; mf++) {
                LDMX4(fa[mf][0], fa[mf][1], fa[mf][2], fa[mf][3],
                      ta + aoff + (uint32_t)mf * (16 * ASTR * 2) + kbyte);
            }
            #pragma unroll
            for (int j = 0; j < 4; j++) {
                if (2 * j < nfmax) {
                    uint32_t r0, r1, r2, r3;
                    LDMX4(r0, r1, r2, r3,
                          tb + boff + (uint32_t)j * (16 * ASTR * 2) + kbyte);
                    fb[2 * j][0] = r0; fb[2 * j][1] = r1;
                    fb[2 * j + 1][0] = r2; fb[2 * j + 1][1] = r3;
                }
            }
            #pragma unroll
            for (int mf = 0; mf < 2; mf++)
                #pragma unroll
                for (int nf = 0; nf < 8; nf++)
                    if (nf < nfmax)
                        mma_f16(acc[mf][nf], fa[mf], fb[nf]);
        }
        __syncthreads();
    }

    // ---- epilogue ----
    const bool vtrans = (MODE == 4) && (bz == 2);
    const int bi = m0 / SEQ;
    const int tl0 = m0 % SEQ;

    #pragma unroll
    for (int mf = 0; mf < 2; mf++) {
        #pragma unroll
        for (int half = 0; half < 2; half++) {
            const int mloc = wm + mf * 16 + g + half * 8;
            const int m = m0 + mloc;
            #pragma unroll
            for (int nf = 0; nf < 8; nf++) {
                const int n = n0 + wn + nf * 8 + 2 * t;
                if (n >= nstore) continue;
                float v0 = acc[mf][nf][half * 2 + 0];
                float v1 = acc[mf][nf][half * 2 + 1];
                if (MODE == 2) {
                    v0 = 1.0f / (1.0f + __expf(-v0 * scale));
                    v1 = 1.0f / (1.0f + __expf(-v1 * scale));
                } else {
                    if (bias) { v0 += bias[n]; v1 += bias[n + 1 < NPA ? n + 1 : n]; }
                }
                if (MODE == 4) {
                    if (vtrans) {
                        const int tl = tl0 + mloc;
                        __half* dst = g_vt + ((long long)(bi * NPA + n)) * SEQ + tl;
                        dst[0] = __float2half_rn(v0);
                        if (n + 1 < nstore) dst[SEQ] = __float2half_rn(v1);
                    } else {
                        __half* dst = (bz ? g_kp : g_qp) + (long long)m * KP + n;
                        __half2 h2;
                        h2.x = __float2half_rn(v0);
                        h2.y = __float2half_rn(v1);
                        *(__half2*)dst = h2;
                    }
                } else if (MODE == 3) {
                    float* dst = Cf + bz * sC + (long long)m * ldc + n;
                    dst[0] = v0;
                    if (n + 1 < nstore) dst[1] = v1;
                } else {
                    __half* dst = C + bz * sC + (long long)m * ldc + n;
                    __half2 h2;
                    h2.x = __float2half_rn(v0);
                    h2.y = __float2half_rn(v1);
                    *(__half2*)dst = h2;                 // n even, ldc even
                }
            }
        }
    }
}

// ---------------- host ----------------
extern "C" void kernel_launch(void* const* d_in, const int* in_sizes, int n_in,
                              void* d_out, int out_size)
{
    const float* q  = (const float*)d_in[0];
    const float* k  = (const float*)d_in[1];
    const float* v  = (const float*)d_in[2];
    const float* Wq = (const float*)d_in[3];
    const float* bq = (const float*)d_in[4];
    const float* Wk = (const float*)d_in[5];
    const float* bk = (const float*)d_in[6];
    const float* Wv = (const float*)d_in[7];
    const float* bv = (const float*)d_in[8];
    const float* Wo = (const float*)d_in[9];
    const float* bo = (const float*)d_in[10];
    float* out = (float*)d_out;

    __half *W, *qp, *kp, *vt, *s, *ct;
    float* bb;
    cudaGetSymbolAddress((void**)&W,  g_W);
    cudaGetSymbolAddress((void**)&bb, g_b);
    cudaGetSymbolAddress((void**)&qp, g_qp);
    cudaGetSymbolAddress((void**)&kp, g_kp);
    cudaGetSymbolAddress((void**)&vt, g_vt);
    cudaGetSymbolAddress((void**)&s,  g_s);
    cudaGetSymbolAddress((void**)&ct, g_ct);

    cudaFuncSetAttribute(gemm<0>, cudaFuncAttributeMaxDynamicSharedMemorySize, SMEM_BYTES);
    cudaFuncSetAttribute(gemm<2>, cudaFuncAttributeMaxDynamicSharedMemorySize, SMEM_BYTES);
    cudaFuncSetAttribute(gemm<3>, cudaFuncAttributeMaxDynamicSharedMemorySize, SMEM_BYTES);
    cudaFuncSetAttribute(gemm<4>, cudaFuncAttributeMaxDynamicSharedMemorySize, SMEM_BYTES);

    const float scale = 1.0f / sqrtf((float)DIM);
    const size_t ws = (size_t)NPA * KP;

    prep_x<<<(BT * KP + 255) / 256, 256>>>(q, k, v);
    prep_w<<<(4 * NPA * KP + 255) / 256, 256>>>(Wq, bq, Wk, bk, Wv, bv, Wo, bo);

    // 1) fused QKV projections: grid.z selects input (0=q,1=k,2=v->V^T)
    dim3 gf(3, BT / 128, 3);
    gemm<4><<<gf, 256, SMEM_BYTES>>>(nullptr, 0, KP, nullptr, 0, KP, KP / KC,
                                     nullptr, nullptr, 0, KP, 0, DIM, nullptr, 0.f);

    // 2) scores = sigmoid(qp @ kp^T * scale), per batch [2048,2048]
    dim3 gs(SEQ / 128, SEQ / 128, NB);
    gemm<2><<<gs, 256, SMEM_BYTES>>>(qp, (long long)SEQ * KP, KP,
                                     kp, (long long)SEQ * KP, KP, KP / KC,
                                     s, nullptr, (long long)SEQ * SEQ, SEQ, SEQ, SEQ,
                                     nullptr, scale);

    // 3) ctx = scores @ V   (B = V^T [384, 2048] per batch, K = 2048)
    dim3 gc(3, SEQ / 128, NB);
    gemm<0><<<gc, 256, SMEM_BYTES>>>(s, (long long)SEQ * SEQ, SEQ,
                                     vt, (long long)NPA * SEQ, SEQ, SEQ / KC,
                                     ct, nullptr, (long long)SEQ * KP, KP, KP, DIM,
                                     nullptr, 0.f);

    // 4) out = ctx @ Wo^T + bo  (fp32 exact store, [BT, 257])
    dim3 gp(3, BT / 128, 1);
    gemm<3><<<gp, 256, SMEM_BYTES>>>(ct, 0, KP, W + 3 * ws, 0, KP, KP / KC,
                                     nullptr, out, 0, DIM, DIM, DIM, bb + 3 * NPA, 0.f);
}

// round 11
// speedup vs baseline: 1.9204x; 1.0390x over previous
#include <cuda_runtime.h>
#include <cuda_fp16.h>
#include <cstdint>
#include <math.h>

#define DIM 257
#define SEQ 2048
#define NB  8
#define BT  (NB * SEQ)        // 16384
#define KP  320               // padded K storage (5 chunks of 64)
#define NPA 384               // padded N for B-operand buffers
#define KC  64                // k halves per pipeline chunk (128B rows)
#define ASTR 72               // smem row stride in halves (144B; ldmatrix conflict-free)
#define TILE_B (128 * ASTR * 2)            // bytes per smem tile (18432)
#define SMEM_BYTES (2 * 2 * TILE_B)        // 73728

// ---------------- static device scratch (fp16 storage, fp32 accumulate) ----------------
__device__ __align__(16) __half g_x[3][(size_t)BT * KP];     // padded q,k,v
__device__ __align__(16) __half g_W[4][(size_t)NPA * KP];    // padded weights (K-major)
__device__ float g_b[4][NPA];                                // padded biases (fp32)
__device__ __align__(16) __half g_qp[(size_t)BT * KP];       // projected Q
__device__ __align__(16) __half g_kp[(size_t)BT * KP];       // projected K
__device__ __align__(16) __half g_vt[(size_t)NB * NPA * SEQ];// V projected, transposed [b][n][t]
__device__ __align__(16) __half g_s[(size_t)NB * SEQ * SEQ]; // sigmoid scores
__device__ __align__(16) __half g_ct[(size_t)BT * KP];       // context

// ---------------- helpers ----------------
__device__ __forceinline__ uint32_t s2u(const void* p) {
    uint32_t a;
    asm("{ .reg .u64 t; cvta.to.shared.u64 t, %1; cvt.u32.u64 %0, t; }" : "=r"(a) : "l"(p));
    return a;
}
__device__ __forceinline__ void cp16(uint32_t dst, const void* src) {
    asm volatile("cp.async.cg.shared.global [%0], [%1], 16;" :: "r"(dst), "l"(src));
}
#define LDMX4(r0, r1, r2, r3, addr) \
    asm volatile("ldmatrix.sync.aligned.m8n8.x4.shared.b16 {%0,%1,%2,%3}, [%4];" \
        : "=r"(r0), "=r"(r1), "=r"(r2), "=r"(r3) : "r"(addr))

__device__ __forceinline__ void mma_f16(float* d, const uint32_t* a, const uint32_t* b) {
    asm volatile(
        "mma.sync.aligned.m16n8k16.row.col.f32.f16.f16.f32 "
        "{%0,%1,%2,%3}, {%4,%5,%6,%7}, {%8,%9}, {%0,%1,%2,%3};"
        : "+f"(d[0]), "+f"(d[1]), "+f"(d[2]), "+f"(d[3])
        : "r"(a[0]), "r"(a[1]), "r"(a[2]), "r"(a[3]), "r"(b[0]), "r"(b[1]));
}

// ---------------- prep kernels (pad + fp16 round) ----------------
__global__ void prep_x(const float* __restrict__ q, const float* __restrict__ k,
                       const float* __restrict__ v) {
    int i = blockIdx.x * 256 + threadIdx.x;
    if (i >= BT * KP) return;
    int r = i / KP, c = i - r * KP;
    long long si = (long long)r * DIM + c;
    g_x[0][i] = (c < DIM) ? __float2half_rn(q[si]) : __float2half_rn(0.f);
    g_x[1][i] = (c < DIM) ? __float2half_rn(k[si]) : __float2half_rn(0.f);
    g_x[2][i] = (c < DIM) ? __float2half_rn(v[si]) : __float2half_rn(0.f);
}
__global__ void prep_w(const float* W0, const float* b0, const float* W1, const float* b1,
                       const float* W2, const float* b2, const float* W3, const float* b3) {
    int i = blockIdx.x * 256 + threadIdx.x;
    const float* Ws[4] = {W0, W1, W2, W3};
    const float* bs[4] = {b0, b1, b2, b3};
    const int per = NPA * KP;
    if (i < 4 * per) {
        int w = i / per, rem = i - w * per, r = rem / KP, c = rem - r * KP;
        g_W[w][(size_t)r * KP + c] =
            (r < DIM && c < DIM) ? __float2half_rn(Ws[w][r * DIM + c]) : __float2half_rn(0.f);
    }
    if (i < 4 * NPA) {
        int w = i / NPA, n = i - w * NPA;
        g_b[w][n] = (n < DIM) ? bs[w][n] : 0.f;
    }
}

// ---------------- fp16 tensor-core GEMM: D[m,n] = sum_k A[m,k]*B[n,k] ----------------
// 128x128 CTA tile, 8 warps (256 thr), 32x64 warp tile (4x2 warp grid).
// ldmatrix fragments, m16n8k16 MMA.
// MASKN: runtime nf-mask (nmma) skips padded-N MMAs (compile-time removable).
// ks_last: number of k16 steps executed in the FINAL chunk (1..4) — trims K padding.
// MODE 0: (+bias if non-null) -> fp16 -> C[m*ldc+n], n < nstore
// MODE 2: sigmoid(v*scale) -> fp16 -> C[m*ldc+n]
// MODE 3: +bias -> fp32 exact -> Cf[m*ldc+n], n < nstore  (final out)
// MODE 4: fused QKV: bz selects input/weight/bias from globals; bz<2 -> qp/kp
//         normal store (nstore=KP); bz==2 -> transposed V^T store (nstore=NPA)
template <int MODE, bool MASKN>
__global__ __launch_bounds__(256, 2)
void gemm(const __half* __restrict__ A, long long sA, int lda,
          const __half* __restrict__ B, long long sB, int ldb,
          int kc, int ks_last, __half* __restrict__ C, float* __restrict__ Cf,
          long long sC, int ldc,
          int nstore, int nmma, const float* __restrict__ bias, float scale)
{
    extern __shared__ __align__(16) char sm[];
    const int tid = threadIdx.x, wid = tid >> 5, lane = tid & 31;
    const int g = lane >> 2, t = lane & 3;
    const int lrow = lane & 7, seg = lane >> 3;
    const int bz = blockIdx.z, m0 = blockIdx.y * 128, n0 = blockIdx.x * 128;
    const int wm = (wid >> 1) * 32, wn = (wid & 1) * 64;

    if (MODE == 4) {
        A = g_x[bz]; B = g_W[bz]; bias = g_b[bz];
        nstore = (bz == 2) ? NPA : KP;
    }

    // warp-uniform count of live 8-wide n-fragments in this warp's 64-col slab
    int nfmax = 8;
    if (MASKN) {
        const int nrem = nmma - n0 - wn;
        nfmax = (nrem >= 64) ? 8 : ((nrem > 0) ? ((nrem + 7) >> 3) : 0);
    }

    const __half* Ab = A + (MODE == 4 ? 0 : bz * sA) + (long long)m0 * lda;
    const __half* Bb = B + (MODE == 4 ? 0 : bz * sB) + (long long)n0 * ldb;
    const uint32_t sb = s2u(sm);

    auto load = [&](int ck, int buf) {
        const char* ag = (const char*)(Ab + ck * KC);
        const char* bg = (const char*)(Bb + ck * KC);
        uint32_t da = sb + (uint32_t)buf * (2 * TILE_B);
        uint32_t db = da + TILE_B;
        #pragma unroll
        for (int i = 0; i < 4; i++) {
            int e = tid + i * 256;               // 0..1023
            int r = e >> 3, c = e & 7;
            uint32_t off = (uint32_t)(r * (ASTR * 2) + c * 16);
            cp16(da + off, ag + (long long)r * lda * 2 + c * 16);
            cp16(db + off, bg + (long long)r * ldb * 2 + c * 16);
        }
        asm volatile("cp.async.commit_group;" ::: "memory");
    };

    // per-thread ldmatrix base offsets (bytes within a tile)
    const uint32_t aoff = (uint32_t)((wm + lrow + (seg & 1) * 8) * (ASTR * 2) + (seg >> 1) * 16);
    const uint32_t boff = (uint32_t)((wn + lrow + (seg >> 1) * 8) * (ASTR * 2) + (seg & 1) * 16);

    float acc[2][8][4] = {};
    load(0, 0);

    for (int ck = 0; ck < kc; ++ck) {
        const int buf = ck & 1;
        if (ck + 1 < kc) {
            load(ck + 1, buf ^ 1);
            asm volatile("cp.async.wait_group 1;" ::: "memory");
        } else {
            asm volatile("cp.async.wait_group 0;" ::: "memory");
        }
        __syncthreads();

        const uint32_t ta = sb + (uint32_t)buf * (2 * TILE_B);
        const uint32_t tb = ta + TILE_B;
        const int ksn = (ck == kc - 1) ? ks_last : 4;

        #pragma unroll
        for (int ks = 0; ks < 4; ks++) {        // up to four k16 steps per 64-half chunk
            if (ks >= ksn) break;
            const uint32_t kbyte = (uint32_t)(ks * 32);
            uint32_t fa[2][4], fb[8][2];
            #pragma unroll
            for (int mf = 0; mf < 2; mf++) {
                LDMX4(fa[mf][0], fa[mf][1], fa[mf][2], fa[mf][3],
                      ta + aoff + (uint32_t)mf * (16 * ASTR * 2) + kbyte);
            }
            #pragma unroll
            for (int j = 0; j < 4; j++) {
                if (!MASKN || 2 * j < nfmax) {
                    uint32_t r0, r1, r2, r3;
                    LDMX4(r0, r1, r2, r3,
                          tb + boff + (uint32_t)j * (16 * ASTR * 2) + kbyte);
                    fb[2 * j][0] = r0; fb[2 * j][1] = r1;
                    fb[2 * j + 1][0] = r2; fb[2 * j + 1][1] = r3;
                }
            }
            #pragma unroll
            for (int mf = 0; mf < 2; mf++)
                #pragma unroll
                for (int nf = 0; nf < 8; nf++)
                    if (!MASKN || nf < nfmax)
                        mma_f16(acc[mf][nf], fa[mf], fb[nf]);
        }
        __syncthreads();
    }

    // ---- epilogue ----
    const bool vtrans = (MODE == 4) && (bz == 2);
    const int bi = m0 / SEQ;
    const int tl0 = m0 % SEQ;

    #pragma unroll
    for (int mf = 0; mf < 2; mf++) {
        #pragma unroll
        for (int half = 0; half < 2; half++) {
            const int mloc = wm + mf * 16 + g + half * 8;
            const int m = m0 + mloc;
            #pragma unroll
            for (int nf = 0; nf < 8; nf++) {
                const int n = n0 + wn + nf * 8 + 2 * t;
                if (n >= nstore) continue;
                float v0 = acc[mf][nf][half * 2 + 0];
                float v1 = acc[mf][nf][half * 2 + 1];
                if (MODE == 2) {
                    v0 = 1.0f / (1.0f + __expf(-v0 * scale));
                    v1 = 1.0f / (1.0f + __expf(-v1 * scale));
                } else {
                    if (bias) { v0 += bias[n]; v1 += bias[n + 1 < NPA ? n + 1 : n]; }
                }
                if (MODE == 4) {
                    if (vtrans) {
                        const int tl = tl0 + mloc;
                        __half* dst = g_vt + ((long long)(bi * NPA + n)) * SEQ + tl;
                        dst[0] = __float2half_rn(v0);
                        if (n + 1 < nstore) dst[SEQ] = __float2half_rn(v1);
                    } else {
                        __half* dst = (bz ? g_kp : g_qp) + (long long)m * KP + n;
                        __half2 h2;
                        h2.x = __float2half_rn(v0);
                        h2.y = __float2half_rn(v1);
                        *(__half2*)dst = h2;
                    }
                } else if (MODE == 3) {
                    float* dst = Cf + bz * sC + (long long)m * ldc + n;
                    dst[0] = v0;
                    if (n + 1 < nstore) dst[1] = v1;
                } else {
                    __half* dst = C + bz * sC + (long long)m * ldc + n;
                    __half2 h2;
                    h2.x = __float2half_rn(v0);
                    h2.y = __float2half_rn(v1);
                    *(__half2*)dst = h2;                 // n even, ldc even
                }
            }
        }
    }
}

// ---------------- host ----------------
extern "C" void kernel_launch(void* const* d_in, const int* in_sizes, int n_in,
                              void* d_out, int out_size)
{
    const float* q  = (const float*)d_in[0];
    const float* k  = (const float*)d_in[1];
    const float* v  = (const float*)d_in[2];
    const float* Wq = (const float*)d_in[3];
    const float* bq = (const float*)d_in[4];
    const float* Wk = (const float*)d_in[5];
    const float* bk = (const float*)d_in[6];
    const float* Wv = (const float*)d_in[7];
    const float* bv = (const float*)d_in[8];
    const float* Wo = (const float*)d_in[9];
    const float* bo = (const float*)d_in[10];
    float* out = (float*)d_out;

    __half *W, *qp, *kp, *vt, *s, *ct;
    float* bb;
    cudaGetSymbolAddress((void**)&W,  g_W);
    cudaGetSymbolAddress((void**)&bb, g_b);
    cudaGetSymbolAddress((void**)&qp, g_qp);
    cudaGetSymbolAddress((void**)&kp, g_kp);
    cudaGetSymbolAddress((void**)&vt, g_vt);
    cudaGetSymbolAddress((void**)&s,  g_s);
    cudaGetSymbolAddress((void**)&ct, g_ct);

    cudaFuncSetAttribute((const void*)gemm<0, true>,  cudaFuncAttributeMaxDynamicSharedMemorySize, SMEM_BYTES);
    cudaFuncSetAttribute((const void*)gemm<2, false>, cudaFuncAttributeMaxDynamicSharedMemorySize, SMEM_BYTES);
    cudaFuncSetAttribute((const void*)gemm<3, true>,  cudaFuncAttributeMaxDynamicSharedMemorySize, SMEM_BYTES);
    cudaFuncSetAttribute((const void*)gemm<4, true>,  cudaFuncAttributeMaxDynamicSharedMemorySize, SMEM_BYTES);

    const float scale = 1.0f / sqrtf((float)DIM);
    const size_t ws = (size_t)NPA * KP;

    prep_x<<<(BT * KP + 255) / 256, 256>>>(q, k, v);
    prep_w<<<(4 * NPA * KP + 255) / 256, 256>>>(Wq, bq, Wk, bk, Wv, bv, Wo, bo);

    // 1) fused QKV projections: grid.z selects input (0=q,1=k,2=v->V^T); K=257 -> 17 k16 steps
    dim3 gf(3, BT / 128, 3);
    gemm<4, true><<<gf, 256, SMEM_BYTES>>>(nullptr, 0, KP, nullptr, 0, KP, KP / KC, 1,
                                           nullptr, nullptr, 0, KP, 0, DIM, nullptr, 0.f);

    // 2) scores = sigmoid(qp @ kp^T * scale), per batch [2048,2048]; full N, K=257
    dim3 gs(SEQ / 128, SEQ / 128, NB);
    gemm<2, false><<<gs, 256, SMEM_BYTES>>>(qp, (long long)SEQ * KP, KP,
                                            kp, (long long)SEQ * KP, KP, KP / KC, 1,
                                            s, nullptr, (long long)SEQ * SEQ, SEQ, SEQ, SEQ,
                                            nullptr, scale);

    // 3) ctx = scores @ V   (B = V^T [384, 2048] per batch, K = 2048, full chunks)
    dim3 gc(3, SEQ / 128, NB);
    gemm<0, true><<<gc, 256, SMEM_BYTES>>>(s, (long long)SEQ * SEQ, SEQ,
                                           vt, (long long)NPA * SEQ, SEQ, SEQ / KC, 4,
                                           ct, nullptr, (long long)SEQ * KP, KP, KP, DIM,
                                           nullptr, 0.f);

    // 4) out = ctx @ Wo^T + bo  (fp32 exact store, [BT, 257]); K=257
    dim3 gp(3, BT / 128, 1);
    gemm<3, true><<<gp, 256, SMEM_BYTES>>>(ct, 0, KP, W + 3 * ws, 0, KP, KP / KC, 1,
                                           nullptr, out, 0, DIM, DIM, DIM, bb + 3 * NPA, 0.f);
}